// round 15
// baseline (speedup 1.0000x reference)
#include <cuda_runtime.h>
#include <math.h>

#define NB 8
#define NPOS 1024
#define CDIM 512

__device__ float g_x [NB*NPOS*CDIM];
__device__ float g_t [NB*NPOS*CDIM];
__device__ float g_q [NB*NPOS*CDIM];
__device__ float g_k [NB*NPOS*CDIM];
__device__ float g_v [NB*NPOS*CDIM];
__device__ float g_gt[NB*NPOS*CDIM];
__device__ float g_xo[NB*NPOS*CDIM];
__device__ float g_M [NB*NPOS*NPOS];
__device__ float g_attn[64*64*64];
__device__ float g_F[NB*NPOS];
__device__ float g_G[NB*NPOS];
__device__ float g_tn[NB*NPOS];
__device__ float g_vn[NB*NPOS];
__device__ float g_qinv[NB*CDIM];
__device__ float g_kinv[NB*CDIM];
__device__ double g_part[8192*2];
__device__ float g_shift[NB];
__device__ float g_scale[NB];
__device__ float g_zp[2*8*16*1024];
__device__ unsigned g_ctr;

__device__ __forceinline__ float ex2f(float x){ float r; asm("ex2.approx.f32 %0, %1;" : "=f"(r) : "f"(x)); return r; }
__device__ __forceinline__ float lg2f(float x){ float r; asm("lg2.approx.f32 %0, %1;" : "=f"(r) : "f"(x)); return r; }

__device__ __forceinline__ unsigned tf32r(float x){ unsigned r; asm("cvt.rna.tf32.f32 %0, %1;" : "=r"(r) : "f"(x)); return r; }
__device__ __forceinline__ void tf32_split(float x, unsigned &hi, unsigned &lo){
    hi = tf32r(x);
    lo = tf32r(x - __uint_as_float(hi));
}

#define MMA_TF32(d, a0,a1,a2,a3, b0,b1) \
    asm("mma.sync.aligned.m16n8k8.row.col.f32.tf32.tf32.f32 {%0,%1,%2,%3},{%4,%5,%6,%7},{%8,%9},{%0,%1,%2,%3};" \
        : "+f"((d)[0]),"+f"((d)[1]),"+f"((d)[2]),"+f"((d)[3]) \
        : "r"(a0),"r"(a1),"r"(a2),"r"(a3),"r"(b0),"r"(b1))

struct MPack {
    const float* A[3];
    const float* B[3];
    float*       C[3];
    const float* aux[3];
    int          epi[3];
};

__global__ void transp(const float* __restrict__ in, float* __restrict__ out, int R, int C)
{
    __shared__ float tile[32][33];
    int bz = blockIdx.z;
    const float* ib = in + (long)bz*R*C;
    float* ob = out + (long)bz*R*C;
    int x = blockIdx.x*32 + threadIdx.x;
    int y0 = blockIdx.y*32;
    for (int j = threadIdx.y; j < 32; j += 8)
        tile[j][threadIdx.x] = ib[(long)(y0+j)*C + x];
    __syncthreads();
    int xo = y0 + threadIdx.x;
    int yo0 = blockIdx.x*32;
    for (int j = threadIdx.y; j < 32; j += 8)
        ob[(long)(yo0+j)*R + xo] = tile[threadIdx.x][j];
}

// ---- shared tf32 split-precision mainloop (R9 validated) ----
__device__ __forceinline__ void tf32_mainloop(
    const float* __restrict__ A, const float* __restrict__ Bp,
    int K, int lda, int ldb, int bm, int bn,
    unsigned (*Ah)[132], unsigned (*Al)[132], unsigned (*Bh)[132], unsigned (*Bl)[132],
    float acc[4][4][4], int tid)
{
    int ar = tid>>2, ac = (tid&3)<<2;
    int br = tid>>5, bc = (tid&31)<<2;
    int warp = tid>>5, lane = tid&31;
    int wm = (warp>>2)<<6, wn = (warp&3)<<5;
    int g = lane>>2, tq = lane&3;

    const float* Aq0 = A + (long)(bm+ar   )*lda + ac;
    const float* Aq1 = A + (long)(bm+ar+64)*lda + ac;
    const float* Bq0 = Bp + (long)br*ldb + bn+bc;
    const float* Bq1 = Bp + (long)(br+8)*ldb + bn+bc;

    float4 pa0 = *(const float4*)Aq0;
    float4 pa1 = *(const float4*)Aq1;
    float4 pb0 = *(const float4*)Bq0;
    float4 pb1 = *(const float4*)Bq1;

    for (int kt=0; kt<K; kt+=16) {
        {
            float a0v[4] = {pa0.x,pa0.y,pa0.z,pa0.w};
            float a1v[4] = {pa1.x,pa1.y,pa1.z,pa1.w};
            #pragma unroll
            for (int i=0;i<4;i++) {
                unsigned h,l;
                tf32_split(a0v[i], h, l); Ah[ac+i][ar]=h;    Al[ac+i][ar]=l;
                tf32_split(a1v[i], h, l); Ah[ac+i][ar+64]=h; Al[ac+i][ar+64]=l;
            }
            float b0v[4] = {pb0.x,pb0.y,pb0.z,pb0.w};
            float b1v[4] = {pb1.x,pb1.y,pb1.z,pb1.w};
            #pragma unroll
            for (int i=0;i<4;i++) {
                unsigned h,l;
                tf32_split(b0v[i], h, l); Bh[br  ][bc+i]=h; Bl[br  ][bc+i]=l;
                tf32_split(b1v[i], h, l); Bh[br+8][bc+i]=h; Bl[br+8][bc+i]=l;
            }
        }
        __syncthreads();
        if (kt+16 < K) {
            pa0 = *(const float4*)(Aq0 + kt+16);
            pa1 = *(const float4*)(Aq1 + kt+16);
            pb0 = *(const float4*)(Bq0 + (long)(kt+16)*ldb);
            pb1 = *(const float4*)(Bq1 + (long)(kt+16)*ldb);
        }
        #pragma unroll
        for (int ks=0; ks<16; ks+=8) {
            unsigned a_h[4][4], b_h[4][2];
            #pragma unroll
            for (int mt=0;mt<4;mt++) {
                int m0 = wm + (mt<<4) + g;
                a_h[mt][0] = Ah[ks+tq  ][m0];
                a_h[mt][1] = Ah[ks+tq  ][m0+8];
                a_h[mt][2] = Ah[ks+tq+4][m0];
                a_h[mt][3] = Ah[ks+tq+4][m0+8];
            }
            #pragma unroll
            for (int nt=0;nt<4;nt++) {
                int n0 = wn + (nt<<3) + g;
                b_h[nt][0] = Bh[ks+tq  ][n0];
                b_h[nt][1] = Bh[ks+tq+4][n0];
            }
            #pragma unroll
            for (int mt=0;mt<4;mt++)
                #pragma unroll
                for (int nt=0;nt<4;nt++)
                    MMA_TF32(acc[mt][nt], a_h[mt][0],a_h[mt][1],a_h[mt][2],a_h[mt][3], b_h[nt][0],b_h[nt][1]);
            {
                unsigned a_l[4][4];
                #pragma unroll
                for (int mt=0;mt<4;mt++) {
                    int m0 = wm + (mt<<4) + g;
                    a_l[mt][0] = Al[ks+tq  ][m0];
                    a_l[mt][1] = Al[ks+tq  ][m0+8];
                    a_l[mt][2] = Al[ks+tq+4][m0];
                    a_l[mt][3] = Al[ks+tq+4][m0+8];
                }
                #pragma unroll
                for (int mt=0;mt<4;mt++)
                    #pragma unroll
                    for (int nt=0;nt<4;nt++)
                        MMA_TF32(acc[mt][nt], a_l[mt][0],a_l[mt][1],a_l[mt][2],a_l[mt][3], b_h[nt][0],b_h[nt][1]);
            }
            {
                unsigned b_l[4][2];
                #pragma unroll
                for (int nt=0;nt<4;nt++) {
                    int n0 = wn + (nt<<3) + g;
                    b_l[nt][0] = Bl[ks+tq  ][n0];
                    b_l[nt][1] = Bl[ks+tq+4][n0];
                }
                #pragma unroll
                for (int mt=0;mt<4;mt++)
                    #pragma unroll
                    for (int nt=0;nt<4;nt++)
                        MMA_TF32(acc[mt][nt], a_h[mt][0],a_h[mt][1],a_h[mt][2],a_h[mt][3], b_l[nt][0],b_l[nt][1]);
            }
        }
        __syncthreads();
    }
}

// batched independent GEMMs: z selects (A,B,C,aux,epi); epi runtime-uniform (0 none, 1 +b, 2 gelu)
__global__ void __launch_bounds__(256,2) gemm_multi(MPack p, int M, int N, int K, int lda, int ldb, int ldc)
{
    int bz = blockIdx.z;
    const float* A  = p.A[bz];
    const float* Bp = p.B[bz];
    float* C = p.C[bz];
    const float* aux = p.aux[bz];
    int epi = p.epi[bz];
    int bm = blockIdx.y*128, bn = blockIdx.x*128;
    __shared__ unsigned Ah[16][132], Al[16][132], Bh[16][132], Bl[16][132];
    float acc[4][4][4];
    #pragma unroll
    for (int i=0;i<4;i++)
        #pragma unroll
        for (int j=0;j<4;j++)
            #pragma unroll
            for (int c=0;c<4;c++) acc[i][j][c]=0.f;
    int tid = threadIdx.x;
    tf32_mainloop(A, Bp, K, lda, ldb, bm, bn, Ah, Al, Bh, Bl, acc, tid);

    int warp = tid>>5, lane = tid&31;
    int wm = (warp>>2)<<6, wn = (warp&3)<<5;
    int g = lane>>2, tq = lane&3;
    #pragma unroll
    for (int mt=0;mt<4;mt++) {
        #pragma unroll
        for (int half=0; half<2; half++) {
            int row = bm + wm + (mt<<4) + g + half*8;
            long rb = (long)row*ldc;
            #pragma unroll
            for (int nt=0;nt<4;nt++) {
                int col = bn + wn + (nt<<3) + (tq<<1);
                float o[2];
                #pragma unroll
                for (int u=0;u<2;u++) {
                    float a = acc[mt][nt][half*2+u];
                    int cc = col+u;
                    float vv;
                    if (epi==0) vv = a;
                    else if (epi==1) vv = a + aux[cc];
                    else { float z = a + aux[cc]; vv = 0.5f*z*(1.0f+erff(z*0.7071067811865475f)); }
                    o[u] = vv;
                }
                *(float2*)(C + rb + col) = make_float2(o[0], o[1]);
            }
        }
    }
}

// EPI: 0 none |1 +b |2 gelu(a+b) |3 cost |4 *aux2 |5 +b+aux2  (R9 validated)
template<int EPI, bool TRANSB>
__global__ void __launch_bounds__(256,2) gemm_k(
    const float* __restrict__ A0, const float* __restrict__ B0, float* __restrict__ C0,
    int M, int N, int K, int lda, int ldb, int ldc, long sA, long sB, long sC,
    const float* __restrict__ aux1, const float* __restrict__ aux2)
{
    int bz = blockIdx.z;
    const float* A  = A0 + (long)bz*sA;
    const float* Bp = B0 + (long)bz*sB;
    float* C = C0 + (long)bz*sC;
    int bm = blockIdx.y*128, bn = blockIdx.x*128;
    __shared__ unsigned Ah[16][132], Al[16][132], Bh[16][132], Bl[16][132];
    float acc[4][4][4];
    #pragma unroll
    for (int i=0;i<4;i++)
        #pragma unroll
        for (int j=0;j<4;j++)
            #pragma unroll
            for (int c=0;c<4;c++) acc[i][j][c]=0.f;

    int tid = threadIdx.x;
    int ar = tid>>2, ac = (tid&3)<<2;
    int br = tid>>5, bc = (tid&31)<<2;
    int warp = tid>>5, lane = tid&31;
    int wm = (warp>>2)<<6, wn = (warp&3)<<5;
    int g = lane>>2, tq = lane&3;

    const float* Aq0 = A + (long)(bm+ar   )*lda + ac;
    const float* Aq1 = A + (long)(bm+ar+64)*lda + ac;
    const float* Bq0;
    const float* Bq1;
    if (TRANSB) { Bq0 = Bp + (long)(bn+ar)*ldb + ac; Bq1 = Bp + (long)(bn+ar+64)*ldb + ac; }
    else        { Bq0 = Bp + (long)br*ldb + bn+bc;   Bq1 = Bp + (long)(br+8)*ldb + bn+bc; }

    float4 pa0 = *(const float4*)Aq0;
    float4 pa1 = *(const float4*)Aq1;
    float4 pb0 = *(const float4*)Bq0;
    float4 pb1 = *(const float4*)Bq1;

    for (int kt=0; kt<K; kt+=16) {
        {
            float a0v[4] = {pa0.x,pa0.y,pa0.z,pa0.w};
            float a1v[4] = {pa1.x,pa1.y,pa1.z,pa1.w};
            #pragma unroll
            for (int i=0;i<4;i++) {
                unsigned h,l;
                tf32_split(a0v[i], h, l); Ah[ac+i][ar]=h;    Al[ac+i][ar]=l;
                tf32_split(a1v[i], h, l); Ah[ac+i][ar+64]=h; Al[ac+i][ar+64]=l;
            }
            float b0v[4] = {pb0.x,pb0.y,pb0.z,pb0.w};
            float b1v[4] = {pb1.x,pb1.y,pb1.z,pb1.w};
            if (TRANSB) {
                #pragma unroll
                for (int i=0;i<4;i++) {
                    unsigned h,l;
                    tf32_split(b0v[i], h, l); Bh[ac+i][ar]=h;    Bl[ac+i][ar]=l;
                    tf32_split(b1v[i], h, l); Bh[ac+i][ar+64]=h; Bl[ac+i][ar+64]=l;
                }
            } else {
                #pragma unroll
                for (int i=0;i<4;i++) {
                    unsigned h,l;
                    tf32_split(b0v[i], h, l); Bh[br  ][bc+i]=h; Bl[br  ][bc+i]=l;
                    tf32_split(b1v[i], h, l); Bh[br+8][bc+i]=h; Bl[br+8][bc+i]=l;
                }
            }
        }
        __syncthreads();
        if (kt+16 < K) {
            pa0 = *(const float4*)(Aq0 + kt+16);
            pa1 = *(const float4*)(Aq1 + kt+16);
            if (TRANSB) { pb0 = *(const float4*)(Bq0 + kt+16); pb1 = *(const float4*)(Bq1 + kt+16); }
            else        { pb0 = *(const float4*)(Bq0 + (long)(kt+16)*ldb); pb1 = *(const float4*)(Bq1 + (long)(kt+16)*ldb); }
        }
        #pragma unroll
        for (int ks=0; ks<16; ks+=8) {
            unsigned a_h[4][4], b_h[4][2];
            #pragma unroll
            for (int mt=0;mt<4;mt++) {
                int m0 = wm + (mt<<4) + g;
                a_h[mt][0] = Ah[ks+tq  ][m0];
                a_h[mt][1] = Ah[ks+tq  ][m0+8];
                a_h[mt][2] = Ah[ks+tq+4][m0];
                a_h[mt][3] = Ah[ks+tq+4][m0+8];
            }
            #pragma unroll
            for (int nt=0;nt<4;nt++) {
                int n0 = wn + (nt<<3) + g;
                b_h[nt][0] = Bh[ks+tq  ][n0];
                b_h[nt][1] = Bh[ks+tq+4][n0];
            }
            #pragma unroll
            for (int mt=0;mt<4;mt++)
                #pragma unroll
                for (int nt=0;nt<4;nt++)
                    MMA_TF32(acc[mt][nt], a_h[mt][0],a_h[mt][1],a_h[mt][2],a_h[mt][3], b_h[nt][0],b_h[nt][1]);
            {
                unsigned a_l[4][4];
                #pragma unroll
                for (int mt=0;mt<4;mt++) {
                    int m0 = wm + (mt<<4) + g;
                    a_l[mt][0] = Al[ks+tq  ][m0];
                    a_l[mt][1] = Al[ks+tq  ][m0+8];
                    a_l[mt][2] = Al[ks+tq+4][m0];
                    a_l[mt][3] = Al[ks+tq+4][m0+8];
                }
                #pragma unroll
                for (int mt=0;mt<4;mt++)
                    #pragma unroll
                    for (int nt=0;nt<4;nt++)
                        MMA_TF32(acc[mt][nt], a_l[mt][0],a_l[mt][1],a_l[mt][2],a_l[mt][3], b_h[nt][0],b_h[nt][1]);
            }
            {
                unsigned b_l[4][2];
                #pragma unroll
                for (int nt=0;nt<4;nt++) {
                    int n0 = wn + (nt<<3) + g;
                    b_l[nt][0] = Bl[ks+tq  ][n0];
                    b_l[nt][1] = Bl[ks+tq+4][n0];
                }
                #pragma unroll
                for (int mt=0;mt<4;mt++)
                    #pragma unroll
                    for (int nt=0;nt<4;nt++)
                        MMA_TF32(acc[mt][nt], a_h[mt][0],a_h[mt][1],a_h[mt][2],a_h[mt][3], b_l[nt][0],b_l[nt][1]);
            }
        }
        __syncthreads();
    }

    #pragma unroll
    for (int mt=0;mt<4;mt++) {
        #pragma unroll
        for (int half=0; half<2; half++) {
            int row = bm + wm + (mt<<4) + g + half*8;
            long rb = (long)row*ldc;
            #pragma unroll
            for (int nt=0;nt<4;nt++) {
                int col = bn + wn + (nt<<3) + (tq<<1);
                float o[2];
                #pragma unroll
                for (int u=0;u<2;u++) {
                    float a = acc[mt][nt][half*2+u];
                    int cc = col+u;
                    float vv;
                    if (EPI==0) vv = a;
                    else if (EPI==1) vv = a + aux1[cc];
                    else if (EPI==2) { float z = a + aux1[cc]; vv = 0.5f*z*(1.0f+erff(z*0.7071067811865475f)); }
                    else if (EPI==3) vv = aux1[bz*M+row] + aux2[bz*N+cc] - 2.0f*a;
                    else if (EPI==4) vv = a * aux2[(long)bz*sC + rb + cc];
                    else              vv = a + aux1[cc] + aux2[(long)bz*sC + rb + cc];
                    o[u] = vv;
                }
                *(float2*)(C + rb + col) = make_float2(o[0], o[1]);
            }
        }
    }
}

__global__ void __launch_bounds__(256) rownorm(const float* __restrict__ X, float* __restrict__ out)
{
    int w = threadIdx.x>>5, l = threadIdx.x&31;
    int row = blockIdx.x*8 + w;
    const float* r = X + (long)row*CDIM;
    float s = 0.f;
    #pragma unroll
    for (int u=0;u<16;u++){ float v = r[l + (u<<5)]; s += v*v; }
    #pragma unroll
    for (int o=16;o;o>>=1) s += __shfl_xor_sync(0xffffffffu, s, o);
    if (l==0) out[row] = s;
}

__global__ void __launch_bounds__(256) colnorm_inv(const float* __restrict__ X, float* __restrict__ out)
{
    __shared__ float sh[256];
    int b = blockIdx.y;
    int t = threadIdx.x;
    int c = blockIdx.x*64 + (t&63);
    int rc = t>>6;
    const float* Xb = X + (long)b*NPOS*CDIM;
    float s = 0.f;
    for (int i = rc*256; i < rc*256+256; i++) { float v = Xb[(long)i*CDIM + c]; s += v*v; }
    sh[t] = s;
    __syncthreads();
    if (rc==0) {
        s = sh[t] + sh[t+64] + sh[t+128] + sh[t+192];
        out[b*CDIM + c] = 1.0f / fmaxf(sqrtf(s), 1e-12f);
    }
}

__global__ void __launch_bounds__(256) stats1(const float* __restrict__ M, double* __restrict__ part)
{
    __shared__ double s1s[256], s2s[256];
    long base = (long)blockIdx.x*1024 + threadIdx.x*4;
    float4 m4 = *(const float4*)(M + base);
    double s1 = (double)m4.x + (double)m4.y + (double)m4.z + (double)m4.w;
    double s2 = (double)m4.x*m4.x + (double)m4.y*m4.y + (double)m4.z*m4.z + (double)m4.w*m4.w;
    s1s[threadIdx.x]=s1; s2s[threadIdx.x]=s2;
    __syncthreads();
    for (int o=128;o;o>>=1){ if(threadIdx.x<o){ s1s[threadIdx.x]+=s1s[threadIdx.x+o]; s2s[threadIdx.x]+=s2s[threadIdx.x+o]; } __syncthreads(); }
    if (threadIdx.x==0){ part[blockIdx.x*2]=s1s[0]; part[blockIdx.x*2+1]=s2s[0]; }
}

__global__ void __launch_bounds__(256) stats2(const double* __restrict__ part, float* __restrict__ shift, float* __restrict__ scale)
{
    __shared__ double s1s[256], s2s[256];
    int b = blockIdx.x;
    double s1=0.0, s2=0.0;
    #pragma unroll
    for (int u=0;u<4;u++){ int idx = b*1024 + threadIdx.x + 256*u; s1 += part[idx*2]; s2 += part[idx*2+1]; }
    s1s[threadIdx.x]=s1; s2s[threadIdx.x]=s2;
    __syncthreads();
    for (int o=128;o;o>>=1){ if(threadIdx.x<o){ s1s[threadIdx.x]+=s1s[threadIdx.x+o]; s2s[threadIdx.x]+=s2s[threadIdx.x+o]; } __syncthreads(); }
    if (threadIdx.x==0){
        double n = 1048576.0;
        double mean = s1s[0]/n;
        double sd = sqrt(s2s[0]/n - mean*mean);
        shift[b] = (float)mean;
        scale[b] = (float)(28.85390081777927 / sd);  // log2(e)/eps/std
    }
}

__global__ void __launch_bounds__(256) mtransform(float* __restrict__ M, const float* __restrict__ shift, const float* __restrict__ scale)
{
    int b = blockIdx.x >> 10;
    float sh = shift[b], sc = scale[b];
    long idx = (long)blockIdx.x*1024 + threadIdx.x*4;
    float4 v = *(const float4*)(M + idx);
    v.x=(v.x-sh)*sc; v.y=(v.y-sh)*sc; v.z=(v.z-sh)*sc; v.w=(v.w-sh)*sc;
    *(float4*)(M + idx) = v;
}

__global__ void initFG(float* __restrict__ F, float* __restrict__ G)
{
    int i = blockIdx.x*256 + threadIdx.x;
    F[i]=0.f; G[i]=0.f;
}

__global__ void zero_ctr()
{
    if (threadIdx.x==0) g_ctr = 0u;
}

__global__ void __launch_bounds__(256) sink_row(const float* __restrict__ Ms, const float* __restrict__ G, float* __restrict__ F)
{
    __shared__ float Gs[1024];
    int b = blockIdx.x >> 7;
    const float* Gb = G + b*1024;
    for (int i = threadIdx.x; i < 1024; i += 256) Gs[i] = Gb[i];
    __syncthreads();
    int w = threadIdx.x>>5, l = threadIdx.x&31;
    int row = ((blockIdx.x & 127) << 3) + w;
    const float* Mr = Ms + ((long)(b*1024 + row))*1024;
    float x[32];
    float m = -3.0e38f;
    #pragma unroll
    for (int u=0;u<32;u++){ int j = l + (u<<5); float vv = Gs[j] - Mr[j]; x[u]=vv; m = fmaxf(m,vv); }
    #pragma unroll
    for (int o=16;o;o>>=1) m = fmaxf(m, __shfl_xor_sync(0xffffffffu, m, o));
    float s = 0.f;
    #pragma unroll
    for (int u=0;u<32;u++) s += ex2f(x[u]-m);
    #pragma unroll
    for (int o=16;o;o>>=1) s += __shfl_xor_sync(0xffffffffu, s, o);
    if (l==0) F[b*1024+row] = -10.0f - m - lg2f(s);
}

__global__ void __launch_bounds__(256) sink_col(const float* __restrict__ Ms, const float* __restrict__ F, float* __restrict__ G)
{
    __shared__ float Fs[1024];
    __shared__ float shm[256], shs[256];
    int b = blockIdx.x >> 5;
    int cc = blockIdx.x & 31;
    const float* Fb = F + b*1024;
    for (int i = threadIdx.x; i < 1024; i += 256) Fs[i] = Fb[i];
    __syncthreads();
    int t = threadIdx.x;
    int c = (cc<<5) + (t&31);
    int rc = t>>5;
    const float* Mb = Ms + (long)b*NPOS*NPOS + c;
    float m = -3.0e38f, s = 0.f;
    for (int i0 = rc*128; i0 < rc*128+128; i0 += 8) {
        float xv[8]; float cm = -3.0e38f;
        #pragma unroll
        for (int u=0;u<8;u++){ float vv = Fs[i0+u] - Mb[(long)(i0+u)<<10]; xv[u]=vv; cm=fmaxf(cm,vv); }
        float mn = fmaxf(m, cm);
        float acc2 = s * ex2f(m - mn);
        #pragma unroll
        for (int u=0;u<8;u++) acc2 += ex2f(xv[u]-mn);
        s = acc2; m = mn;
    }
    shm[t]=m; shs[t]=s;
    __syncthreads();
    if (rc==0) {
        float M0 = m, S = s;
        #pragma unroll
        for (int r=1;r<8;r++){
            float mr = shm[t + (r<<5)], sr = shs[t + (r<<5)];
            float mn = fmaxf(M0, mr);
            S = S*ex2f(M0-mn) + sr*ex2f(mr-mn);
            M0 = mn;
        }
        G[b*1024 + c] = -10.0f - M0 - lg2f(S);
    }
}

// Knn_ij = 2^(F_i + G_j - Ms_ij)  (in-place safe)
__global__ void __launch_bounds__(256) plan_k(const float* __restrict__ Ms, const float* __restrict__ F,
                                              const float* __restrict__ G, float* __restrict__ P)
{
    int b = blockIdx.y, i = blockIdx.x;
    float Fi = F[b*1024 + i];
    const float* Gb = G + b*1024;
    long base = ((long)(b*1024 + i))*1024 + threadIdx.x*4;
    int j = threadIdx.x*4;
    float4 m4 = *(const float4*)(Ms + base);
    float4 p;
    p.x = ex2f(Fi + Gb[j  ] - m4.x);
    p.y = ex2f(Fi + Gb[j+1] - m4.y);
    p.z = ex2f(Fi + Gb[j+2] - m4.z);
    p.w = ex2f(Fi + Gb[j+3] - m4.w);
    *(float4*)(P + base) = p;
}

__device__ __forceinline__ void gridbar128(unsigned target)
{
    __threadfence();
    __syncthreads();
    if (threadIdx.x == 0) {
        atomicAdd(&g_ctr, 1u);
        while (*(volatile unsigned*)&g_ctr < target) {}
        __threadfence();
    }
    __syncthreads();
}

// persistent scaled-Sinkhorn: ONE Knn sweep + ONE grid barrier per iteration.
// Knn rows are block-private and read-only during iterations -> cached (L1) loads;
// only cross-block data (zp) uses __ldcg.
__global__ void __launch_bounds__(512,1) sink_persist2(float* __restrict__ Knn, float* __restrict__ zp)
{
    extern __shared__ float sh[];
    float* v_sh = sh;                 // 1024
    float* u_sh = sh + 1024;          // 64
    float* zred = sh + 1024 + 64;     // 16*1024
    int blk = blockIdx.x, t = threadIdx.x;
    int batch = blk >> 4;
    int slot = blk & 15;
    int row0 = slot << 6;
    long Mbase = (long)batch << 20;
    int w = t >> 5, l = t & 31;
    const float inv_n = 0.0009765625f;
    unsigned nb = 0;

    for (int i = t; i < 1024; i += 512) v_sh[i] = 1.0f;
    __syncthreads();

    for (int it = 0; it < 99; it++) {
        float zr[32];
        #pragma unroll
        for (int u=0;u<32;u++) zr[u]=0.f;
        #pragma unroll
        for (int k = 0; k < 4; k++) {
            int r = (w<<2) + k;
            const float4* Mr = (const float4*)(Knn + Mbase + ((long)(row0 + r) << 10));
            float4 rv[8];
            #pragma unroll
            for (int u=0;u<8;u++) rv[u] = Mr[l + (u<<5)];
            float s = 0.f;
            #pragma unroll
            for (int u=0;u<8;u++) {
                const float4 vv = *(const float4*)&v_sh[(l<<2) + (u<<7)];
                s += rv[u].x*vv.x + rv[u].y*vv.y + rv[u].z*vv.z + rv[u].w*vv.w;
            }
            #pragma unroll
            for (int o=16;o;o>>=1) s += __shfl_xor_sync(0xffffffffu, s, o);
            float ur = inv_n / s;
            if (l == 0) u_sh[r] = ur;
            #pragma unroll
            for (int u=0;u<8;u++) {
                zr[4*u+0] += rv[u].x * ur;
                zr[4*u+1] += rv[u].y * ur;
                zr[4*u+2] += rv[u].z * ur;
                zr[4*u+3] += rv[u].w * ur;
            }
        }
        #pragma unroll
        for (int u=0;u<8;u++)
            *(float4*)&zred[(w<<10) + (l<<2) + (u<<7)] =
                make_float4(zr[4*u], zr[4*u+1], zr[4*u+2], zr[4*u+3]);
        __syncthreads();
        nb++;
        long pbase = ((long)(nb & 1) << 17) + (batch << 14);
        {
            float z0 = 0.f, z1 = 0.f;
            #pragma unroll
            for (int s16=0; s16<16; s16++) {
                float2 zz = *(const float2*)&zred[(s16<<10) + (t<<1)];
                z0 += zz.x; z1 += zz.y;
            }
            *(float2*)&zp[pbase + (slot<<10) + (t<<1)] = make_float2(z0, z1);
        }
        gridbar128(nb * 128);
        {
            float s0 = 0.f, s1 = 0.f;
            #pragma unroll
            for (int s16=0; s16<16; s16++) {
                s0 += __ldcg(&zp[pbase + (s16<<10) + (t<<1)]);
                s1 += __ldcg(&zp[pbase + (s16<<10) + (t<<1) + 1]);
            }
            v_sh[(t<<1)    ] = inv_n / s0;
            v_sh[(t<<1) + 1] = inv_n / s1;
        }
        __syncthreads();
    }

    // final: P = Knn * u_i * v_j (in place, own rows only)
    #pragma unroll
    for (int k = 0; k < 4; k++) {
        int r = (w<<2) + k;
        float ur = u_sh[r];
        float4* Mr = (float4*)(Knn + Mbase + ((long)(row0 + r) << 10));
        #pragma unroll
        for (int u=0;u<8;u++) {
            float4 m = Mr[l + (u<<5)];
            const float4 vv = *(const float4*)&v_sh[(l<<2) + (u<<7)];
            m.x *= ur*vv.x; m.y *= ur*vv.y; m.z *= ur*vv.z; m.w *= ur*vv.w;
            Mr[l + (u<<5)] = m;
        }
    }
}

// fused channel-attn scores + softmax; one block per (b,h)
__global__ void __launch_bounds__(256) attn_fused(const float* __restrict__ q, const float* __restrict__ k,
                                                  const float* __restrict__ kinv, const float* __restrict__ qinv,
                                                  const float* __restrict__ rescale, float* __restrict__ attn)
{
    __shared__ float ks[32][68], qs[32][68], sm[64][65];
    int bh = blockIdx.x;
    int b = bh>>3, h = bh&7;
    int t = threadIdx.x;
    int lr = t>>3, lc = (t&7)<<3;
    const float* kb = k + (long)b*NPOS*CDIM + h*64;
    const float* qb = q + (long)b*NPOS*CDIM + h*64;
    int d0 = (t>>4)<<2, e0 = (t&15)<<2;
    float acc[4][4];
    #pragma unroll
    for (int i=0;i<4;i++)
        #pragma unroll
        for (int j=0;j<4;j++) acc[i][j]=0.f;
    for (int i0 = 0; i0 < 1024; i0 += 32) {
        const float* krow = kb + (long)(i0+lr)*CDIM + lc;
        const float* qrow = qb + (long)(i0+lr)*CDIM + lc;
        *(float4*)&ks[lr][lc  ] = *(const float4*)(krow  );
        *(float4*)&ks[lr][lc+4] = *(const float4*)(krow+4);
        *(float4*)&qs[lr][lc  ] = *(const float4*)(qrow  );
        *(float4*)&qs[lr][lc+4] = *(const float4*)(qrow+4);
        __syncthreads();
        #pragma unroll 8
        for (int kk=0; kk<32; kk++) {
            float a[4], bb[4];
            *(float4*)a  = *(const float4*)&ks[kk][d0];
            *(float4*)bb = *(const float4*)&qs[kk][e0];
            #pragma unroll
            for (int i=0;i<4;i++)
                #pragma unroll
                for (int j=0;j<4;j++)
                    acc[i][j] += a[i]*bb[j];
        }
        __syncthreads();
    }
    float rs = rescale[h];
    #pragma unroll
    for (int i=0;i<4;i++) {
        float ki = kinv[b*CDIM + h*64 + d0+i] * rs;
        #pragma unroll
        for (int j=0;j<4;j++)
            sm[d0+i][e0+j] = acc[i][j] * ki * qinv[b*CDIM + h*64 + e0+j];
    }
    __syncthreads();
    if (t < 64) {
        float m = -3.0e38f;
        #pragma unroll
        for (int e=0;e<64;e++) m = fmaxf(m, sm[t][e]);
        float s = 0.f;
        float vals[64];
        #pragma unroll
        for (int e=0;e<64;e++){ float p = ex2f((sm[t][e]-m)*1.4426950408889634f); vals[e]=p; s+=p; }
        float inv = 1.0f/s;
        #pragma unroll
        for (int e=0;e<64;e++) attn[(long)bh*4096 + t*64 + e] = vals[e]*inv;
    }
}

// xo[b,i,h*64+d] = sum_e guided[b,i,h*64+e] * attn[bh,d,e]
__global__ void __launch_bounds__(256) xo_k(const float* __restrict__ gt, const float* __restrict__ attn, float* __restrict__ xo)
{
    __shared__ float gs[64][68], at[64][68];
    int i0 = blockIdx.x*64, h = blockIdx.y, b = blockIdx.z;
    int t = threadIdx.x;
    int r = t>>2, c0 = (t&3)<<4;
    const float* gb = gt + (long)(b*NPOS + i0 + r)*CDIM + h*64;
    const float* ab = attn + (long)(b*8 + h)*4096 + r*64;
    #pragma unroll
    for (int u=0;u<16;u+=4) {
        *(float4*)&gs[r][c0+u] = *(const float4*)(gb + c0+u);
        *(float4*)&at[r][c0+u] = *(const float4*)(ab + c0+u);
    }
    __syncthreads();
    int i = t & 63;
    int d0 = (t>>6)<<4;
    float acc[16];
    #pragma unroll
    for (int u=0;u<16;u++) acc[u]=0.f;
    for (int e=0; e<64; e+=4) {
        float4 g4 = *(const float4*)&gs[i][e];
        #pragma unroll
        for (int dd=0; dd<16; dd++) {
            float4 a4 = *(const float4*)&at[d0+dd][e];
            acc[dd] += g4.x*a4.x + g4.y*a4.y + g4.z*a4.z + g4.w*a4.w;
        }
    }
    float* ob = xo + (long)(b*NPOS + i0 + i)*CDIM + h*64 + d0;
    #pragma unroll
    for (int u=0;u<16;u+=4) *(float4*)(ob+u) = make_float4(acc[u],acc[u+1],acc[u+2],acc[u+3]);
}

extern "C" void kernel_launch(void* const* d_in, const int* in_sizes, int n_in,
                              void* d_out, int out_size)
{
    const float* x_in    = (const float*)d_in[0];
    const float* task_x  = (const float*)d_in[1];
    const float* Wq      = (const float*)d_in[2];
    const float* Wk      = (const float*)d_in[3];
    const float* Wv      = (const float*)d_in[4];
    const float* rescale = (const float*)d_in[5];
    const float* Wp      = (const float*)d_in[6];
    const float* bp      = (const float*)d_in[7];
    const float* W1      = (const float*)d_in[8];
    const float* b1      = (const float*)d_in[9];
    const float* W2      = (const float*)d_in[10];
    const float* b2      = (const float*)d_in[11];
    float* out = (float*)d_out;

    float *px,*pt,*pq,*pk,*pv,*pgt,*pxo,*pM,*pattn,*pF,*pG,*ptn,*pvn,*pqinv,*pkinv,*pshift,*pscale,*pzp;
    double* ppart;
    cudaGetSymbolAddress((void**)&px, g_x);
    cudaGetSymbolAddress((void**)&pt, g_t);
    cudaGetSymbolAddress((void**)&pq, g_q);
    cudaGetSymbolAddress((void**)&pk, g_k);
    cudaGetSymbolAddress((void**)&pv, g_v);
    cudaGetSymbolAddress((void**)&pgt, g_gt);
    cudaGetSymbolAddress((void**)&pxo, g_xo);
    cudaGetSymbolAddress((void**)&pM, g_M);
    cudaGetSymbolAddress((void**)&pattn, g_attn);
    cudaGetSymbolAddress((void**)&pF, g_F);
    cudaGetSymbolAddress((void**)&pG, g_G);
    cudaGetSymbolAddress((void**)&ptn, g_tn);
    cudaGetSymbolAddress((void**)&pvn, g_vn);
    cudaGetSymbolAddress((void**)&pqinv, g_qinv);
    cudaGetSymbolAddress((void**)&pkinv, g_kinv);
    cudaGetSymbolAddress((void**)&ppart, g_part);
    cudaGetSymbolAddress((void**)&pshift, g_shift);
    cudaGetSymbolAddress((void**)&pscale, g_scale);
    cudaGetSymbolAddress((void**)&pzp, g_zp);

    const long SN = (long)NPOS*CDIM;
    const long SM = (long)NPOS*NPOS;
    const int SINK_SMEM = (1024 + 64 + 16*1024) * 4;
    cudaFuncSetAttribute(sink_persist2, cudaFuncAttributeMaxDynamicSharedMemorySize, SINK_SMEM);
    dim3 tb(32,8);

    // channel-last x, t
    transp<<<dim3(32,16,NB), tb>>>(x_in,  px, CDIM, NPOS);
    transp<<<dim3(32,16,NB), tb>>>(task_x, pt, CDIM, NPOS);

    // QKV: one wave-packed launch (z selects weight/output)
    {
        MPack p;
        p.A[0]=px; p.A[1]=px; p.A[2]=px;
        p.B[0]=Wq; p.B[1]=Wk; p.B[2]=Wv;
        p.C[0]=pq; p.C[1]=pk; p.C[2]=pv;
        p.aux[0]=nullptr; p.aux[1]=nullptr; p.aux[2]=nullptr;
        p.epi[0]=0; p.epi[1]=0; p.epi[2]=0;
        gemm_multi<<<dim3(4,64,3),256>>>(p, 8192, 512, 512, 512, 512, 512);
    }

    // row norms for cost
    rownorm<<<1024,256>>>(pt, ptn);
    rownorm<<<1024,256>>>(pv, pvn);

    // cost M = |t|^2 + |v|^2 - 2 t.v
    gemm_k<3,true><<<dim3(8,8,NB),256>>>(pt, pv, pM, 1024, 1024, 512, 512,512,1024, SN,SN,SM, ptn, pvn);

    // standardize (fp64 stats) and pre-scale to log2 units
    stats1<<<8192,256>>>(pM, ppart);
    stats2<<<NB,256>>>(ppart, pshift, pscale);
    mtransform<<<8192,256>>>(pM, pshift, pscale);

    // Sinkhorn: 1 log-domain warmup iteration (bounds kernel entries by ~1/n)
    initFG<<<32,256>>>(pF, pG);
    sink_row<<<1024,256>>>(pM, pG, pF);
    sink_col<<<256,256>>>(pM, pF, pG);
    // Knn = 2^(F+G-Ms), in place
    plan_k<<<dim3(1024,NB),256>>>(pM, pF, pG, pM);
    // remaining 99 iterations: fused one-sweep persistent kernel + final plan write
    zero_ctr<<<1,32>>>();
    sink_persist2<<<128,512,SINK_SMEM>>>(pM, pzp);

    // guided = (P @ t) * v   (P lives in pM)
    gemm_k<4,false><<<dim3(4,8,NB),256>>>(pM, pt, pgt, 1024, 512, 1024, 1024,512,512, SM,SN,SN, nullptr, pv);

    // channel attention
    colnorm_inv<<<dim3(8,NB),256>>>(pq, pqinv);
    colnorm_inv<<<dim3(8,NB),256>>>(pk, pkinv);
    attn_fused<<<64,256>>>(pq, pk, pkinv, pqinv, rescale, pattn);
    xo_k<<<dim3(16,8,NB),256>>>(pgt, pattn, pxo);

    // independent pair: out_c = xo@Wp+bp (epi=1, into pq) and hidden = gelu(v@W1+b1) (epi=2, into px)
    {
        MPack p;
        p.A[0]=pxo; p.A[1]=pv;  p.A[2]=nullptr;
        p.B[0]=Wp;  p.B[1]=W1;  p.B[2]=nullptr;
        p.C[0]=pq;  p.C[1]=px;  p.C[2]=nullptr;
        p.aux[0]=bp; p.aux[1]=b1; p.aux[2]=nullptr;
        p.epi[0]=1; p.epi[1]=2; p.epi[2]=0;
        gemm_multi<<<dim3(4,64,2),256>>>(p, 8192, 512, 512, 512, 512, 512);
    }

    // final = hidden @ W2 + b2 + out_c  (into pxo)
    gemm_k<5,false><<<dim3(4,64,1),256>>>(px, W2, pxo, 8192, 512, 512, 512,512,512, 0,0,0, b2, pq);

    // [b,n,c] -> [b,c,n]
    transp<<<dim3(16,32,NB), tb>>>(pxo, out, NPOS, CDIM);
}

// round 16
// speedup vs baseline: 1.3292x; 1.3292x over previous
#include <cuda_runtime.h>
#include <cuda_bf16.h>
#include <math.h>

#define NB 8
#define NPOS 1024
#define CDIM 512

__device__ float g_x [NB*NPOS*CDIM];
__device__ float g_t [NB*NPOS*CDIM];
__device__ float g_q [NB*NPOS*CDIM];
__device__ float g_k [NB*NPOS*CDIM];
__device__ float g_v [NB*NPOS*CDIM];
__device__ float g_gt[NB*NPOS*CDIM];
__device__ float g_xo[NB*NPOS*CDIM];
__device__ float g_M [NB*NPOS*NPOS];
__device__ float g_attn[64*64*64];
__device__ float g_F[NB*NPOS];
__device__ float g_G[NB*NPOS];
__device__ float g_tn[NB*NPOS];
__device__ float g_vn[NB*NPOS];
__device__ float g_qinv[NB*CDIM];
__device__ float g_kinv[NB*CDIM];
__device__ double g_part[8192*2];
__device__ float g_shift[NB];
__device__ float g_scale[NB];
__device__ float g_zp[2*8*16*1024];
__device__ unsigned g_ctr;

__device__ __forceinline__ float ex2f(float x){ float r; asm("ex2.approx.f32 %0, %1;" : "=f"(r) : "f"(x)); return r; }
__device__ __forceinline__ float lg2f(float x){ float r; asm("lg2.approx.f32 %0, %1;" : "=f"(r) : "f"(x)); return r; }

// split x into bf16 hi + bf16 lo (first-order residual); pack two k-adjacent values per uint
__device__ __forceinline__ void pack_split(float x0, float x1, unsigned &H, unsigned &L)
{
    __nv_bfloat16 h0 = __float2bfloat16_rn(x0);
    __nv_bfloat16 h1 = __float2bfloat16_rn(x1);
    __nv_bfloat16 l0 = __float2bfloat16_rn(x0 - __bfloat162float(h0));
    __nv_bfloat16 l1 = __float2bfloat16_rn(x1 - __bfloat162float(h1));
    unsigned short uh0 = *(unsigned short*)&h0, uh1 = *(unsigned short*)&h1;
    unsigned short ul0 = *(unsigned short*)&l0, ul1 = *(unsigned short*)&l1;
    H = ((unsigned)uh1 << 16) | uh0;
    L = ((unsigned)ul1 << 16) | ul0;
}

#define MMA_BF16(d, a0,a1,a2,a3, b0,b1) \
    asm("mma.sync.aligned.m16n8k16.row.col.f32.bf16.bf16.f32 {%0,%1,%2,%3},{%4,%5,%6,%7},{%8,%9},{%0,%1,%2,%3};" \
        : "+f"((d)[0]),"+f"((d)[1]),"+f"((d)[2]),"+f"((d)[3]) \
        : "r"(a0),"r"(a1),"r"(a2),"r"(a3),"r"(b0),"r"(b1))

struct MPack {
    const float* A[3];
    const float* B[3];
    float*       C[3];
    const float* aux[3];
    int          epi[3];
};

__global__ void transp(const float* __restrict__ in, float* __restrict__ out, int R, int C)
{
    __shared__ float tile[32][33];
    int bz = blockIdx.z;
    const float* ib = in + (long)bz*R*C;
    float* ob = out + (long)bz*R*C;
    int x = blockIdx.x*32 + threadIdx.x;
    int y0 = blockIdx.y*32;
    for (int j = threadIdx.y; j < 32; j += 8)
        tile[j][threadIdx.x] = ib[(long)(y0+j)*C + x];
    __syncthreads();
    int xo = y0 + threadIdx.x;
    int yo0 = blockIdx.x*32;
    for (int j = threadIdx.y; j < 32; j += 8)
        ob[(long)(yo0+j)*R + xo] = tile[threadIdx.x][j];
}

// ---- bf16x3 split-precision mainloop (hh + lh + hl), m16n8k16 ----
// Pair-packed smem: row = k-pair index (0..7 for 16 k), col = m/n (0..127).
// Consumer fragment mapping isomorphic to validated R9 tf32 mapping.
template<bool TRANSB>
__device__ __forceinline__ void bf16_mainloop(
    const float* __restrict__ A, const float* __restrict__ Bp,
    int K, int lda, int ldb, int bm, int bn,
    unsigned (*Ah)[132], unsigned (*Al)[132], unsigned (*Bh)[132], unsigned (*Bl)[132],
    float acc[4][4][4], int tid)
{
    int ar = tid>>2, ac = (tid&3)<<2;
    int br = tid>>5, bc = (tid&31)<<2;
    int warp = tid>>5, lane = tid&31;
    int wm = (warp>>2)<<6, wn = (warp&3)<<5;
    int g = lane>>2, tq = lane&3;
    int pr = ac>>1;                       // pair-row base for A-style packing (0,2,4,6)

    const float* Aq0 = A + (long)(bm+ar   )*lda + ac;
    const float* Aq1 = A + (long)(bm+ar+64)*lda + ac;
    const float* Bq0;
    const float* Bq1;
    if (TRANSB) { Bq0 = Bp + (long)(bn+ar)*ldb + ac;      Bq1 = Bp + (long)(bn+ar+64)*ldb + ac; }
    else        { Bq0 = Bp + (long)(2*br)*ldb + bn+bc;    Bq1 = Bp + (long)(2*br+1)*ldb + bn+bc; }

    float4 pa0 = *(const float4*)Aq0;
    float4 pa1 = *(const float4*)Aq1;
    float4 pb0 = *(const float4*)Bq0;
    float4 pb1 = *(const float4*)Bq1;

    for (int kt=0; kt<K; kt+=16) {
        {
            float a0v[4] = {pa0.x,pa0.y,pa0.z,pa0.w};
            float a1v[4] = {pa1.x,pa1.y,pa1.z,pa1.w};
            #pragma unroll
            for (int j=0;j<2;j++) {
                unsigned H,L;
                pack_split(a0v[2*j], a0v[2*j+1], H, L); Ah[pr+j][ar]=H;    Al[pr+j][ar]=L;
                pack_split(a1v[2*j], a1v[2*j+1], H, L); Ah[pr+j][ar+64]=H; Al[pr+j][ar+64]=L;
            }
            float b0v[4] = {pb0.x,pb0.y,pb0.z,pb0.w};
            float b1v[4] = {pb1.x,pb1.y,pb1.z,pb1.w};
            if (TRANSB) {
                // B rows are n; k runs along the float4 (contiguous) -> pack like A
                #pragma unroll
                for (int j=0;j<2;j++) {
                    unsigned H,L;
                    pack_split(b0v[2*j], b0v[2*j+1], H, L); Bh[pr+j][ar]=H;    Bl[pr+j][ar]=L;
                    pack_split(b1v[2*j], b1v[2*j+1], H, L); Bh[pr+j][ar+64]=H; Bl[pr+j][ar+64]=L;
                }
            } else {
                // rows 2br (k even) and 2br+1 (k odd) pack vertically per n
                #pragma unroll
                for (int i=0;i<4;i++) {
                    unsigned H,L;
                    pack_split(b0v[i], b1v[i], H, L);
                    Bh[br][bc+i]=H; Bl[br][bc+i]=L;
                }
            }
        }
        __syncthreads();
        if (kt+16 < K) {
            pa0 = *(const float4*)(Aq0 + kt+16);
            pa1 = *(const float4*)(Aq1 + kt+16);
            if (TRANSB) { pb0 = *(const float4*)(Bq0 + kt+16); pb1 = *(const float4*)(Bq1 + kt+16); }
            else        { pb0 = *(const float4*)(Bq0 + (long)(kt+16)*ldb); pb1 = *(const float4*)(Bq1 + (long)(kt+16)*ldb); }
        }
        {
            unsigned a_h[4][4], b_h[4][2];
            #pragma unroll
            for (int mt=0;mt<4;mt++) {
                int m0 = wm + (mt<<4) + g;
                a_h[mt][0] = Ah[tq  ][m0];
                a_h[mt][1] = Ah[tq  ][m0+8];
                a_h[mt][2] = Ah[tq+4][m0];
                a_h[mt][3] = Ah[tq+4][m0+8];
            }
            #pragma unroll
            for (int nt=0;nt<4;nt++) {
                int n0 = wn + (nt<<3) + g;
                b_h[nt][0] = Bh[tq  ][n0];
                b_h[nt][1] = Bh[tq+4][n0];
            }
            #pragma unroll
            for (int mt=0;mt<4;mt++)
                #pragma unroll
                for (int nt=0;nt<4;nt++)
                    MMA_BF16(acc[mt][nt], a_h[mt][0],a_h[mt][1],a_h[mt][2],a_h[mt][3], b_h[nt][0],b_h[nt][1]);
            {
                unsigned a_l[4][4];
                #pragma unroll
                for (int mt=0;mt<4;mt++) {
                    int m0 = wm + (mt<<4) + g;
                    a_l[mt][0] = Al[tq  ][m0];
                    a_l[mt][1] = Al[tq  ][m0+8];
                    a_l[mt][2] = Al[tq+4][m0];
                    a_l[mt][3] = Al[tq+4][m0+8];
                }
                #pragma unroll
                for (int mt=0;mt<4;mt++)
                    #pragma unroll
                    for (int nt=0;nt<4;nt++)
                        MMA_BF16(acc[mt][nt], a_l[mt][0],a_l[mt][1],a_l[mt][2],a_l[mt][3], b_h[nt][0],b_h[nt][1]);
            }
            {
                unsigned b_l[4][2];
                #pragma unroll
                for (int nt=0;nt<4;nt++) {
                    int n0 = wn + (nt<<3) + g;
                    b_l[nt][0] = Bl[tq  ][n0];
                    b_l[nt][1] = Bl[tq+4][n0];
                }
                #pragma unroll
                for (int mt=0;mt<4;mt++)
                    #pragma unroll
                    for (int nt=0;nt<4;nt++)
                        MMA_BF16(acc[mt][nt], a_h[mt][0],a_h[mt][1],a_h[mt][2],a_h[mt][3], b_l[nt][0],b_l[nt][1]);
            }
        }
        __syncthreads();
    }
}

// batched independent GEMMs (non-transposed B): z selects operands; epi uniform per block
__global__ void __launch_bounds__(256,2) gemm_multi(MPack p, int M, int N, int K, int lda, int ldb, int ldc)
{
    int bz = blockIdx.z;
    const float* A  = p.A[bz];
    const float* Bp = p.B[bz];
    float* C = p.C[bz];
    const float* aux = p.aux[bz];
    int epi = p.epi[bz];
    int bm = blockIdx.y*128, bn = blockIdx.x*128;
    __shared__ unsigned Ah[8][132], Al[8][132], Bh[8][132], Bl[8][132];
    float acc[4][4][4];
    #pragma unroll
    for (int i=0;i<4;i++)
        #pragma unroll
        for (int j=0;j<4;j++)
            #pragma unroll
            for (int c=0;c<4;c++) acc[i][j][c]=0.f;
    int tid = threadIdx.x;
    bf16_mainloop<false>(A, Bp, K, lda, ldb, bm, bn, Ah, Al, Bh, Bl, acc, tid);

    int warp = tid>>5, lane = tid&31;
    int wm = (warp>>2)<<6, wn = (warp&3)<<5;
    int g = lane>>2, tq = lane&3;
    #pragma unroll
    for (int mt=0;mt<4;mt++) {
        #pragma unroll
        for (int half=0; half<2; half++) {
            int row = bm + wm + (mt<<4) + g + half*8;
            long rb = (long)row*ldc;
            #pragma unroll
            for (int nt=0;nt<4;nt++) {
                int col = bn + wn + (nt<<3) + (tq<<1);
                float o[2];
                #pragma unroll
                for (int u=0;u<2;u++) {
                    float a = acc[mt][nt][half*2+u];
                    int cc = col+u;
                    float vv;
                    if (epi==0) vv = a;
                    else if (epi==1) vv = a + aux[cc];
                    else { float z = a + aux[cc]; vv = 0.5f*z*(1.0f+erff(z*0.7071067811865475f)); }
                    o[u] = vv;
                }
                *(float2*)(C + rb + col) = make_float2(o[0], o[1]);
            }
        }
    }
}

// EPI: 0 none |1 +b |2 gelu(a+b) |3 cost |4 *aux2 |5 +b+aux2
template<int EPI, bool TRANSB>
__global__ void __launch_bounds__(256,2) gemm_k(
    const float* __restrict__ A0, const float* __restrict__ B0, float* __restrict__ C0,
    int M, int N, int K, int lda, int ldb, int ldc, long sA, long sB, long sC,
    const float* __restrict__ aux1, const float* __restrict__ aux2)
{
    int bz = blockIdx.z;
    const float* A  = A0 + (long)bz*sA;
    const float* Bp = B0 + (long)bz*sB;
    float* C = C0 + (long)bz*sC;
    int bm = blockIdx.y*128, bn = blockIdx.x*128;
    __shared__ unsigned Ah[8][132], Al[8][132], Bh[8][132], Bl[8][132];
    float acc[4][4][4];
    #pragma unroll
    for (int i=0;i<4;i++)
        #pragma unroll
        for (int j=0;j<4;j++)
            #pragma unroll
            for (int c=0;c<4;c++) acc[i][j][c]=0.f;
    int tid = threadIdx.x;
    bf16_mainloop<TRANSB>(A, Bp, K, lda, ldb, bm, bn, Ah, Al, Bh, Bl, acc, tid);

    int warp = tid>>5, lane = tid&31;
    int wm = (warp>>2)<<6, wn = (warp&3)<<5;
    int g = lane>>2, tq = lane&3;
    #pragma unroll
    for (int mt=0;mt<4;mt++) {
        #pragma unroll
        for (int half=0; half<2; half++) {
            int row = bm + wm + (mt<<4) + g + half*8;
            long rb = (long)row*ldc;
            #pragma unroll
            for (int nt=0;nt<4;nt++) {
                int col = bn + wn + (nt<<3) + (tq<<1);
                float o[2];
                #pragma unroll
                for (int u=0;u<2;u++) {
                    float a = acc[mt][nt][half*2+u];
                    int cc = col+u;
                    float vv;
                    if (EPI==0) vv = a;
                    else if (EPI==1) vv = a + aux1[cc];
                    else if (EPI==2) { float z = a + aux1[cc]; vv = 0.5f*z*(1.0f+erff(z*0.7071067811865475f)); }
                    else if (EPI==3) vv = aux1[bz*M+row] + aux2[bz*N+cc] - 2.0f*a;
                    else if (EPI==4) vv = a * aux2[(long)bz*sC + rb + cc];
                    else              vv = a + aux1[cc] + aux2[(long)bz*sC + rb + cc];
                    o[u] = vv;
                }
                *(float2*)(C + rb + col) = make_float2(o[0], o[1]);
            }
        }
    }
}

__global__ void __launch_bounds__(256) rownorm(const float* __restrict__ X, float* __restrict__ out)
{
    int w = threadIdx.x>>5, l = threadIdx.x&31;
    int row = blockIdx.x*8 + w;
    const float* r = X + (long)row*CDIM;
    float s = 0.f;
    #pragma unroll
    for (int u=0;u<16;u++){ float v = r[l + (u<<5)]; s += v*v; }
    #pragma unroll
    for (int o=16;o;o>>=1) s += __shfl_xor_sync(0xffffffffu, s, o);
    if (l==0) out[row] = s;
}

__global__ void __launch_bounds__(256) colnorm_inv(const float* __restrict__ X, float* __restrict__ out)
{
    __shared__ float sh[256];
    int b = blockIdx.y;
    int t = threadIdx.x;
    int c = blockIdx.x*64 + (t&63);
    int rc = t>>6;
    const float* Xb = X + (long)b*NPOS*CDIM;
    float s = 0.f;
    for (int i = rc*256; i < rc*256+256; i++) { float v = Xb[(long)i*CDIM + c]; s += v*v; }
    sh[t] = s;
    __syncthreads();
    if (rc==0) {
        s = sh[t] + sh[t+64] + sh[t+128] + sh[t+192];
        out[b*CDIM + c] = 1.0f / fmaxf(sqrtf(s), 1e-12f);
    }
}

__global__ void __launch_bounds__(256) stats1(const float* __restrict__ M, double* __restrict__ part)
{
    __shared__ double s1s[256], s2s[256];
    long base = (long)blockIdx.x*1024 + threadIdx.x*4;
    float4 m4 = *(const float4*)(M + base);
    double s1 = (double)m4.x + (double)m4.y + (double)m4.z + (double)m4.w;
    double s2 = (double)m4.x*m4.x + (double)m4.y*m4.y + (double)m4.z*m4.z + (double)m4.w*m4.w;
    s1s[threadIdx.x]=s1; s2s[threadIdx.x]=s2;
    __syncthreads();
    for (int o=128;o;o>>=1){ if(threadIdx.x<o){ s1s[threadIdx.x]+=s1s[threadIdx.x+o]; s2s[threadIdx.x]+=s2s[threadIdx.x+o]; } __syncthreads(); }
    if (threadIdx.x==0){ part[blockIdx.x*2]=s1s[0]; part[blockIdx.x*2+1]=s2s[0]; }
}

__global__ void __launch_bounds__(256) stats2(const double* __restrict__ part, float* __restrict__ shift, float* __restrict__ scale)
{
    __shared__ double s1s[256], s2s[256];
    int b = blockIdx.x;
    double s1=0.0, s2=0.0;
    #pragma unroll
    for (int u=0;u<4;u++){ int idx = b*1024 + threadIdx.x + 256*u; s1 += part[idx*2]; s2 += part[idx*2+1]; }
    s1s[threadIdx.x]=s1; s2s[threadIdx.x]=s2;
    __syncthreads();
    for (int o=128;o;o>>=1){ if(threadIdx.x<o){ s1s[threadIdx.x]+=s1s[threadIdx.x+o]; s2s[threadIdx.x]+=s2s[threadIdx.x+o]; } __syncthreads(); }
    if (threadIdx.x==0){
        double n = 1048576.0;
        double mean = s1s[0]/n;
        double sd = sqrt(s2s[0]/n - mean*mean);
        shift[b] = (float)mean;
        scale[b] = (float)(28.85390081777927 / sd);  // log2(e)/eps/std
    }
}

__global__ void __launch_bounds__(256) mtransform(float* __restrict__ M, const float* __restrict__ shift, const float* __restrict__ scale)
{
    int b = blockIdx.x >> 10;
    float sh = shift[b], sc = scale[b];
    long idx = (long)blockIdx.x*1024 + threadIdx.x*4;
    float4 v = *(const float4*)(M + idx);
    v.x=(v.x-sh)*sc; v.y=(v.y-sh)*sc; v.z=(v.z-sh)*sc; v.w=(v.w-sh)*sc;
    *(float4*)(M + idx) = v;
}

__global__ void initFG(float* __restrict__ F, float* __restrict__ G)
{
    int i = blockIdx.x*256 + threadIdx.x;
    F[i]=0.f; G[i]=0.f;
}

__global__ void zero_ctr()
{
    if (threadIdx.x==0) g_ctr = 0u;
}

__global__ void __launch_bounds__(256) sink_row(const float* __restrict__ Ms, const float* __restrict__ G, float* __restrict__ F)
{
    __shared__ float Gs[1024];
    int b = blockIdx.x >> 7;
    const float* Gb = G + b*1024;
    for (int i = threadIdx.x; i < 1024; i += 256) Gs[i] = Gb[i];
    __syncthreads();
    int w = threadIdx.x>>5, l = threadIdx.x&31;
    int row = ((blockIdx.x & 127) << 3) + w;
    const float* Mr = Ms + ((long)(b*1024 + row))*1024;
    float x[32];
    float m = -3.0e38f;
    #pragma unroll
    for (int u=0;u<32;u++){ int j = l + (u<<5); float vv = Gs[j] - Mr[j]; x[u]=vv; m = fmaxf(m,vv); }
    #pragma unroll
    for (int o=16;o;o>>=1) m = fmaxf(m, __shfl_xor_sync(0xffffffffu, m, o));
    float s = 0.f;
    #pragma unroll
    for (int u=0;u<32;u++) s += ex2f(x[u]-m);
    #pragma unroll
    for (int o=16;o;o>>=1) s += __shfl_xor_sync(0xffffffffu, s, o);
    if (l==0) F[b*1024+row] = -10.0f - m - lg2f(s);
}

__global__ void __launch_bounds__(256) sink_col(const float* __restrict__ Ms, const float* __restrict__ F, float* __restrict__ G)
{
    __shared__ float Fs[1024];
    __shared__ float shm[256], shs[256];
    int b = blockIdx.x >> 5;
    int cc = blockIdx.x & 31;
    const float* Fb = F + b*1024;
    for (int i = threadIdx.x; i < 1024; i += 256) Fs[i] = Fb[i];
    __syncthreads();
    int t = threadIdx.x;
    int c = (cc<<5) + (t&31);
    int rc = t>>5;
    const float* Mb = Ms + (long)b*NPOS*NPOS + c;
    float m = -3.0e38f, s = 0.f;
    for (int i0 = rc*128; i0 < rc*128+128; i0 += 8) {
        float xv[8]; float cm = -3.0e38f;
        #pragma unroll
        for (int u=0;u<8;u++){ float vv = Fs[i0+u] - Mb[(long)(i0+u)<<10]; xv[u]=vv; cm=fmaxf(cm,vv); }
        float mn = fmaxf(m, cm);
        float acc2 = s * ex2f(m - mn);
        #pragma unroll
        for (int u=0;u<8;u++) acc2 += ex2f(xv[u]-mn);
        s = acc2; m = mn;
    }
    shm[t]=m; shs[t]=s;
    __syncthreads();
    if (rc==0) {
        float M0 = m, S = s;
        #pragma unroll
        for (int r=1;r<8;r++){
            float mr = shm[t + (r<<5)], sr = shs[t + (r<<5)];
            float mn = fmaxf(M0, mr);
            S = S*ex2f(M0-mn) + sr*ex2f(mr-mn);
            M0 = mn;
        }
        G[b*1024 + c] = -10.0f - M0 - lg2f(S);
    }
}

// Knn_ij = 2^(F_i + G_j - Ms_ij)  (in-place safe)
__global__ void __launch_bounds__(256) plan_k(const float* __restrict__ Ms, const float* __restrict__ F,
                                              const float* __restrict__ G, float* __restrict__ P)
{
    int b = blockIdx.y, i = blockIdx.x;
    float Fi = F[b*1024 + i];
    const float* Gb = G + b*1024;
    long base = ((long)(b*1024 + i))*1024 + threadIdx.x*4;
    int j = threadIdx.x*4;
    float4 m4 = *(const float4*)(Ms + base);
    float4 p;
    p.x = ex2f(Fi + Gb[j  ] - m4.x);
    p.y = ex2f(Fi + Gb[j+1] - m4.y);
    p.z = ex2f(Fi + Gb[j+2] - m4.z);
    p.w = ex2f(Fi + Gb[j+3] - m4.w);
    *(float4*)(P + base) = p;
}

__device__ __forceinline__ void gridbar128(unsigned target)
{
    __threadfence();
    __syncthreads();
    if (threadIdx.x == 0) {
        atomicAdd(&g_ctr, 1u);
        while (*(volatile unsigned*)&g_ctr < target) {}
        __threadfence();
    }
    __syncthreads();
}

// persistent scaled-Sinkhorn (validated R6/R14 config, __ldcg on Knn)
__global__ void __launch_bounds__(512,1) sink_persist2(float* __restrict__ Knn, float* __restrict__ zp)
{
    extern __shared__ float sh[];
    float* v_sh = sh;                 // 1024
    float* u_sh = sh + 1024;          // 64
    float* zred = sh + 1024 + 64;     // 16*1024
    int blk = blockIdx.x, t = threadIdx.x;
    int batch = blk >> 4;
    int slot = blk & 15;
    int row0 = slot << 6;
    long Mbase = (long)batch << 20;
    int w = t >> 5, l = t & 31;
    const float inv_n = 0.0009765625f;
    unsigned nb = 0;

    for (int i = t; i < 1024; i += 512) v_sh[i] = 1.0f;
    __syncthreads();

    for (int it = 0; it < 99; it++) {
        float zr[32];
        #pragma unroll
        for (int u=0;u<32;u++) zr[u]=0.f;
        #pragma unroll
        for (int k = 0; k < 4; k++) {
            int r = (w<<2) + k;
            const float4* Mr = (const float4*)(Knn + Mbase + ((long)(row0 + r) << 10));
            float4 rv[8];
            #pragma unroll
            for (int u=0;u<8;u++) rv[u] = __ldcg(&Mr[l + (u<<5)]);
            float s = 0.f;
            #pragma unroll
            for (int u=0;u<8;u++) {
                const float4 vv = *(const float4*)&v_sh[(l<<2) + (u<<7)];
                s += rv[u].x*vv.x + rv[u].y*vv.y + rv[u].z*vv.z + rv[u].w*vv.w;
            }
            #pragma unroll
            for (int o=16;o;o>>=1) s += __shfl_xor_sync(0xffffffffu, s, o);
            float ur = inv_n / s;
            if (l == 0) u_sh[r] = ur;
            #pragma unroll
            for (int u=0;u<8;u++) {
                zr[4*u+0] += rv[u].x * ur;
                zr[4*u+1] += rv[u].y * ur;
                zr[4*u+2] += rv[u].z * ur;
                zr[4*u+3] += rv[u].w * ur;
            }
        }
        #pragma unroll
        for (int u=0;u<8;u++)
            *(float4*)&zred[(w<<10) + (l<<2) + (u<<7)] =
                make_float4(zr[4*u], zr[4*u+1], zr[4*u+2], zr[4*u+3]);
        __syncthreads();
        nb++;
        long pbase = ((long)(nb & 1) << 17) + (batch << 14);
        {
            float z0 = 0.f, z1 = 0.f;
            #pragma unroll
            for (int s16=0; s16<16; s16++) {
                float2 zz = *(const float2*)&zred[(s16<<10) + (t<<1)];
                z0 += zz.x; z1 += zz.y;
            }
            *(float2*)&zp[pbase + (slot<<10) + (t<<1)] = make_float2(z0, z1);
        }
        gridbar128(nb * 128);
        {
            float s0 = 0.f, s1 = 0.f;
            #pragma unroll
            for (int s16=0; s16<16; s16++) {
                s0 += __ldcg(&zp[pbase + (s16<<10) + (t<<1)]);
                s1 += __ldcg(&zp[pbase + (s16<<10) + (t<<1) + 1]);
            }
            v_sh[(t<<1)    ] = inv_n / s0;
            v_sh[(t<<1) + 1] = inv_n / s1;
        }
        __syncthreads();
    }

    #pragma unroll
    for (int k = 0; k < 4; k++) {
        int r = (w<<2) + k;
        float ur = u_sh[r];
        float4* Mr = (float4*)(Knn + Mbase + ((long)(row0 + r) << 10));
        #pragma unroll
        for (int u=0;u<8;u++) {
            float4 m = __ldcg(&Mr[l + (u<<5)]);
            const float4 vv = *(const float4*)&v_sh[(l<<2) + (u<<7)];
            m.x *= ur*vv.x; m.y *= ur*vv.y; m.z *= ur*vv.z; m.w *= ur*vv.w;
            Mr[l + (u<<5)] = m;
        }
    }
}

__global__ void __launch_bounds__(256) attn_fused(const float* __restrict__ q, const float* __restrict__ k,
                                                  const float* __restrict__ kinv, const float* __restrict__ qinv,
                                                  const float* __restrict__ rescale, float* __restrict__ attn)
{
    __shared__ float ks[32][68], qs[32][68], sm[64][65];
    int bh = blockIdx.x;
    int b = bh>>3, h = bh&7;
    int t = threadIdx.x;
    int lr = t>>3, lc = (t&7)<<3;
    const float* kb = k + (long)b*NPOS*CDIM + h*64;
    const float* qb = q + (long)b*NPOS*CDIM + h*64;
    int d0 = (t>>4)<<2, e0 = (t&15)<<2;
    float acc[4][4];
    #pragma unroll
    for (int i=0;i<4;i++)
        #pragma unroll
        for (int j=0;j<4;j++) acc[i][j]=0.f;
    for (int i0 = 0; i0 < 1024; i0 += 32) {
        const float* krow = kb + (long)(i0+lr)*CDIM + lc;
        const float* qrow = qb + (long)(i0+lr)*CDIM + lc;
        *(float4*)&ks[lr][lc  ] = *(const float4*)(krow  );
        *(float4*)&ks[lr][lc+4] = *(const float4*)(krow+4);
        *(float4*)&qs[lr][lc  ] = *(const float4*)(qrow  );
        *(float4*)&qs[lr][lc+4] = *(const float4*)(qrow+4);
        __syncthreads();
        #pragma unroll 8
        for (int kk=0; kk<32; kk++) {
            float a[4], bb[4];
            *(float4*)a  = *(const float4*)&ks[kk][d0];
            *(float4*)bb = *(const float4*)&qs[kk][e0];
            #pragma unroll
            for (int i=0;i<4;i++)
                #pragma unroll
                for (int j=0;j<4;j++)
                    acc[i][j] += a[i]*bb[j];
        }
        __syncthreads();
    }
    float rs = rescale[h];
    #pragma unroll
    for (int i=0;i<4;i++) {
        float ki = kinv[b*CDIM + h*64 + d0+i] * rs;
        #pragma unroll
        for (int j=0;j<4;j++)
            sm[d0+i][e0+j] = acc[i][j] * ki * qinv[b*CDIM + h*64 + e0+j];
    }
    __syncthreads();
    if (t < 64) {
        float m = -3.0e38f;
        #pragma unroll
        for (int e=0;e<64;e++) m = fmaxf(m, sm[t][e]);
        float s = 0.f;
        float vals[64];
        #pragma unroll
        for (int e=0;e<64;e++){ float p = ex2f((sm[t][e]-m)*1.4426950408889634f); vals[e]=p; s+=p; }
        float inv = 1.0f/s;
        #pragma unroll
        for (int e=0;e<64;e++) attn[(long)bh*4096 + t*64 + e] = vals[e]*inv;
    }
}

__global__ void __launch_bounds__(256) xo_k(const float* __restrict__ gt, const float* __restrict__ attn, float* __restrict__ xo)
{
    __shared__ float gs[64][68], at[64][68];
    int i0 = blockIdx.x*64, h = blockIdx.y, b = blockIdx.z;
    int t = threadIdx.x;
    int r = t>>2, c0 = (t&3)<<4;
    const float* gb = gt + (long)(b*NPOS + i0 + r)*CDIM + h*64;
    const float* ab = attn + (long)(b*8 + h)*4096 + r*64;
    #pragma unroll
    for (int u=0;u<16;u+=4) {
        *(float4*)&gs[r][c0+u] = *(const float4*)(gb + c0+u);
        *(float4*)&at[r][c0+u] = *(const float4*)(ab + c0+u);
    }
    __syncthreads();
    int i = t & 63;
    int d0 = (t>>6)<<4;
    float acc[16];
    #pragma unroll
    for (int u=0;u<16;u++) acc[u]=0.f;
    for (int e=0; e<64; e+=4) {
        float4 g4 = *(const float4*)&gs[i][e];
        #pragma unroll
        for (int dd=0; dd<16; dd++) {
            float4 a4 = *(const float4*)&at[d0+dd][e];
            acc[dd] += g4.x*a4.x + g4.y*a4.y + g4.z*a4.z + g4.w*a4.w;
        }
    }
    float* ob = xo + (long)(b*NPOS + i0 + i)*CDIM + h*64 + d0;
    #pragma unroll
    for (int u=0;u<16;u+=4) *(float4*)(ob+u) = make_float4(acc[u],acc[u+1],acc[u+2],acc[u+3]);
}

extern "C" void kernel_launch(void* const* d_in, const int* in_sizes, int n_in,
                              void* d_out, int out_size)
{
    const float* x_in    = (const float*)d_in[0];
    const float* task_x  = (const float*)d_in[1];
    const float* Wq      = (const float*)d_in[2];
    const float* Wk      = (const float*)d_in[3];
    const float* Wv      = (const float*)d_in[4];
    const float* rescale = (const float*)d_in[5];
    const float* Wp      = (const float*)d_in[6];
    const float* bp      = (const float*)d_in[7];
    const float* W1      = (const float*)d_in[8];
    const float* b1      = (const float*)d_in[9];
    const float* W2      = (const float*)d_in[10];
    const float* b2      = (const float*)d_in[11];
    float* out = (float*)d_out;

    float *px,*pt,*pq,*pk,*pv,*pgt,*pxo,*pM,*pattn,*pF,*pG,*ptn,*pvn,*pqinv,*pkinv,*pshift,*pscale,*pzp;
    double* ppart;
    cudaGetSymbolAddress((void**)&px, g_x);
    cudaGetSymbolAddress((void**)&pt, g_t);
    cudaGetSymbolAddress((void**)&pq, g_q);
    cudaGetSymbolAddress((void**)&pk, g_k);
    cudaGetSymbolAddress((void**)&pv, g_v);
    cudaGetSymbolAddress((void**)&pgt, g_gt);
    cudaGetSymbolAddress((void**)&pxo, g_xo);
    cudaGetSymbolAddress((void**)&pM, g_M);
    cudaGetSymbolAddress((void**)&pattn, g_attn);
    cudaGetSymbolAddress((void**)&pF, g_F);
    cudaGetSymbolAddress((void**)&pG, g_G);
    cudaGetSymbolAddress((void**)&ptn, g_tn);
    cudaGetSymbolAddress((void**)&pvn, g_vn);
    cudaGetSymbolAddress((void**)&pqinv, g_qinv);
    cudaGetSymbolAddress((void**)&pkinv, g_kinv);
    cudaGetSymbolAddress((void**)&ppart, g_part);
    cudaGetSymbolAddress((void**)&pshift, g_shift);
    cudaGetSymbolAddress((void**)&pscale, g_scale);
    cudaGetSymbolAddress((void**)&pzp, g_zp);

    const long SN = (long)NPOS*CDIM;
    const long SM = (long)NPOS*NPOS;
    const int SINK_SMEM = (1024 + 64 + 16*1024) * 4;
    cudaFuncSetAttribute(sink_persist2, cudaFuncAttributeMaxDynamicSharedMemorySize, SINK_SMEM);
    dim3 tb(32,8);

    // channel-last x, t
    transp<<<dim3(32,16,NB), tb>>>(x_in,  px, CDIM, NPOS);
    transp<<<dim3(32,16,NB), tb>>>(task_x, pt, CDIM, NPOS);

    // QKV: wave-packed
    {
        MPack p;
        p.A[0]=px; p.A[1]=px; p.A[2]=px;
        p.B[0]=Wq; p.B[1]=Wk; p.B[2]=Wv;
        p.C[0]=pq; p.C[1]=pk; p.C[2]=pv;
        p.aux[0]=nullptr; p.aux[1]=nullptr; p.aux[2]=nullptr;
        p.epi[0]=0; p.epi[1]=0; p.epi[2]=0;
        gemm_multi<<<dim3(4,64,3),256>>>(p, 8192, 512, 512, 512, 512, 512);
    }

    // row norms for cost
    rownorm<<<1024,256>>>(pt, ptn);
    rownorm<<<1024,256>>>(pv, pvn);

    // cost M = |t|^2 + |v|^2 - 2 t.v
    gemm_k<3,true><<<dim3(8,8,NB),256>>>(pt, pv, pM, 1024, 1024, 512, 512,512,1024, SN,SN,SM, ptn, pvn);

    // standardize and pre-scale to log2 units
    stats1<<<8192,256>>>(pM, ppart);
    stats2<<<NB,256>>>(ppart, pshift, pscale);
    mtransform<<<8192,256>>>(pM, pshift, pscale);

    // Sinkhorn: 1 log-domain warmup iteration
    initFG<<<32,256>>>(pF, pG);
    sink_row<<<1024,256>>>(pM, pG, pF);
    sink_col<<<256,256>>>(pM, pF, pG);
    plan_k<<<dim3(1024,NB),256>>>(pM, pF, pG, pM);
    zero_ctr<<<1,32>>>();
    sink_persist2<<<128,512,SINK_SMEM>>>(pM, pzp);

    // guided = (P @ t) * v
    gemm_k<4,false><<<dim3(4,8,NB),256>>>(pM, pt, pgt, 1024, 512, 1024, 1024,512,512, SM,SN,SN, nullptr, pv);

    // channel attention
    colnorm_inv<<<dim3(8,NB),256>>>(pq, pqinv);
    colnorm_inv<<<dim3(8,NB),256>>>(pk, pkinv);
    attn_fused<<<64,256>>>(pq, pk, pkinv, pqinv, rescale, pattn);
    xo_k<<<dim3(16,8,NB),256>>>(pgt, pattn, pxo);

    // out_c and hidden, wave-packed
    {
        MPack p;
        p.A[0]=pxo; p.A[1]=pv;  p.A[2]=nullptr;
        p.B[0]=Wp;  p.B[1]=W1;  p.B[2]=nullptr;
        p.C[0]=pq;  p.C[1]=px;  p.C[2]=nullptr;
        p.aux[0]=bp; p.aux[1]=b1; p.aux[2]=nullptr;
        p.epi[0]=1; p.epi[1]=2; p.epi[2]=0;
        gemm_multi<<<dim3(4,64,2),256>>>(p, 8192, 512, 512, 512, 512, 512);
    }

    // final = hidden @ W2 + b2 + out_c
    gemm_k<5,false><<<dim3(4,64,1),256>>>(px, W2, pxo, 8192, 512, 512, 512,512,512, 0,0,0, b2, pq);

    // [b,n,c] -> [b,c,n]
    transp<<<dim3(16,32,NB), tb>>>(pxo, out, NPOS, CDIM);
}